// round 1
// baseline (speedup 1.0000x reference)
#include <cuda_runtime.h>

// Problem constants
#define DD      512          // d_model
#define HK      2048         // H*DK
#define NB      1024         // batch
#define LSLOTS  50           // memory slots
#define HOPN    3.0f
#define KSPLIT  8
#define KCHUNK  (HK / KSPLIT)   // 256

// Scratch (static device globals — no allocation)
__device__ float g_Wpart[KSPLIT * DD * DD];   // 8 MB split-K partials
__device__ float g_W[DD * DD];                // fused weight wv@wo
__device__ float g_c[DD];                     // fused bias bv@wo + bo
__device__ float g_temp[NB * DD];             // scaled temp = 3w*(hid@W + c)

// ---------------------------------------------------------------------------
// Kernel 1: Wpart[ks][i,j] = sum_{k in chunk ks} wv[i,k] * wo[k,j]
// 64x64 tile, 256 threads, 4x4 micro, K-step 16, split-K over z.
// ---------------------------------------------------------------------------
__global__ __launch_bounds__(256) void k_gemm_w(const float* __restrict__ wv,
                                                const float* __restrict__ wo) {
    __shared__ float As[16][64];   // As[kk][ii]
    __shared__ float Bs[16][64];   // Bs[kk][jj]
    const int tj = blockIdx.x * 64;
    const int ti = blockIdx.y * 64;
    const int ks = blockIdx.z;
    const int t  = threadIdx.x;
    const int tx = t & 15;         // 0..15 -> j micro
    const int ty = t >> 4;         // 0..15 -> i micro

    float acc[4][4];
#pragma unroll
    for (int i = 0; i < 4; i++)
#pragma unroll
        for (int j = 0; j < 4; j++) acc[i][j] = 0.0f;

    const int kbase = ks * KCHUNK;
    for (int k0 = 0; k0 < KCHUNK; k0 += 16) {
        // load A tile (64 rows x 16 k), transposed into As[kk][ii]
#pragma unroll
        for (int s = 0; s < 4; s++) {
            int e  = t + s * 256;          // 0..1023
            int ii = e >> 4, kk = e & 15;
            As[kk][ii] = wv[(ti + ii) * HK + kbase + k0 + kk];
        }
        // load B tile (16 k x 64 j)
#pragma unroll
        for (int s = 0; s < 4; s++) {
            int e  = t + s * 256;
            int kk = e >> 6, jj = e & 63;
            Bs[kk][jj] = wo[(kbase + k0 + kk) * DD + tj + jj];
        }
        __syncthreads();
#pragma unroll
        for (int kk = 0; kk < 16; kk++) {
            float4 a4 = *(const float4*)&As[kk][ty * 4];
            float4 b4 = *(const float4*)&Bs[kk][tx * 4];
            float av[4] = {a4.x, a4.y, a4.z, a4.w};
            float bvv[4] = {b4.x, b4.y, b4.z, b4.w};
#pragma unroll
            for (int i = 0; i < 4; i++)
#pragma unroll
                for (int j = 0; j < 4; j++) acc[i][j] += av[i] * bvv[j];
        }
        __syncthreads();
    }

    float* out = g_Wpart + ks * DD * DD;
#pragma unroll
    for (int i = 0; i < 4; i++) {
        int row = ti + ty * 4 + i;
#pragma unroll
        for (int j = 0; j < 4; j++)
            out[row * DD + tj + tx * 4 + j] = acc[i][j];
    }
}

// ---------------------------------------------------------------------------
// Kernel 2: W = sum over KSPLIT partials (float4)
// grid 256 x 256 threads covers DD*DD/4 = 65536 float4
// ---------------------------------------------------------------------------
__global__ __launch_bounds__(256) void k_reduce_w() {
    int i = blockIdx.x * blockDim.x + threadIdx.x;   // float4 index
    const float4* p = (const float4*)g_Wpart;
    float4 s = p[i];
#pragma unroll
    for (int k = 1; k < KSPLIT; k++) {
        float4 v = p[k * (DD * DD / 4) + i];
        s.x += v.x; s.y += v.y; s.z += v.z; s.w += v.w;
    }
    ((float4*)g_W)[i] = s;
}

// ---------------------------------------------------------------------------
// Kernel 3: c[j] = sum_k bv[k]*wo[k,j] + bo[j]
// grid 16 blocks, each handles 32 j's, 8 k-groups of 256
// ---------------------------------------------------------------------------
__global__ __launch_bounds__(256) void k_bias_c(const float* __restrict__ bv,
                                                const float* __restrict__ wo,
                                                const float* __restrict__ bo) {
    __shared__ float red[256];
    const int j0 = blockIdx.x * 32;
    const int t  = threadIdx.x;
    const int tj = t & 31;
    const int kg = t >> 5;
    float acc = 0.0f;
    const int kb = kg * 256;
    for (int k = kb; k < kb + 256; k++)
        acc += bv[k] * wo[k * DD + j0 + tj];
    red[t] = acc;
    __syncthreads();
    if (kg == 0) {
        float s = acc;
#pragma unroll
        for (int g = 1; g < 8; g++) s += red[tj + 32 * g];
        g_c[j0 + tj] = s + bo[j0 + tj];
    }
}

// ---------------------------------------------------------------------------
// Kernel 4: temp[b,j] = 3*w * ( sum_d hid[b,d]*W[d,j] + c[j] )
// 64x64 tile, grid (8 j-tiles, 16 b-tiles)
// ---------------------------------------------------------------------------
__global__ __launch_bounds__(256) void k_gemm_temp(const float* __restrict__ hid,
                                                   const float* __restrict__ wsc) {
    __shared__ float As[16][64];
    __shared__ float Bs[16][64];
    const int tj = blockIdx.x * 64;
    const int tb = blockIdx.y * 64;
    const int t  = threadIdx.x;
    const int tx = t & 15;
    const int ty = t >> 4;

    float acc[4][4];
#pragma unroll
    for (int i = 0; i < 4; i++)
#pragma unroll
        for (int j = 0; j < 4; j++) acc[i][j] = 0.0f;

    for (int k0 = 0; k0 < DD; k0 += 16) {
#pragma unroll
        for (int s = 0; s < 4; s++) {
            int e  = t + s * 256;
            int ii = e >> 4, kk = e & 15;
            As[kk][ii] = hid[(tb + ii) * DD + k0 + kk];
        }
#pragma unroll
        for (int s = 0; s < 4; s++) {
            int e  = t + s * 256;
            int kk = e >> 6, jj = e & 63;
            Bs[kk][jj] = g_W[(k0 + kk) * DD + tj + jj];
        }
        __syncthreads();
#pragma unroll
        for (int kk = 0; kk < 16; kk++) {
            float4 a4 = *(const float4*)&As[kk][ty * 4];
            float4 b4 = *(const float4*)&Bs[kk][tx * 4];
            float av[4] = {a4.x, a4.y, a4.z, a4.w};
            float bvv[4] = {b4.x, b4.y, b4.z, b4.w};
#pragma unroll
            for (int i = 0; i < 4; i++)
#pragma unroll
                for (int j = 0; j < 4; j++) acc[i][j] += av[i] * bvv[j];
        }
        __syncthreads();
    }

    const float s = HOPN * wsc[0];
    float cj[4];
#pragma unroll
    for (int j = 0; j < 4; j++) cj[j] = g_c[tj + tx * 4 + j];
#pragma unroll
    for (int i = 0; i < 4; i++) {
        int row = tb + ty * 4 + i;
#pragma unroll
        for (int j = 0; j < 4; j++)
            g_temp[row * DD + tj + tx * 4 + j] = s * (acc[i][j] + cj[j]);
    }
}

// ---------------------------------------------------------------------------
// Kernel 5: out[l,b,d] = momery[l,b,d] + temp[b,d]   (temp already scaled)
// float4, broadcast over L via index mask (B*D is a power of two)
// ---------------------------------------------------------------------------
#define BD4 (NB * DD / 4)   // 131072, power of two

__global__ __launch_bounds__(256) void k_add(const float4* __restrict__ mom,
                                             float4* __restrict__ out, int n4) {
    const float4* tp = (const float4*)g_temp;
    int stride = gridDim.x * blockDim.x;
    for (int i = blockIdx.x * blockDim.x + threadIdx.x; i < n4; i += stride) {
        float4 m = mom[i];
        float4 t = tp[i & (BD4 - 1)];
        m.x += t.x; m.y += t.y; m.z += t.z; m.w += t.w;
        out[i] = m;
    }
}

// ---------------------------------------------------------------------------
// Launch. Inputs (metadata order):
// 0 momery, 1 hid, 2 text_polarity, 3 attribute_polarity, 4 w,
// 5 p_w1, 6 p_b1, 7 p_w2, 8 p_b2, 9 wq, 10 bq, 11 wk, 12 bk,
// 13 wv, 14 bv, 15 wo, 16 bo
// ---------------------------------------------------------------------------
extern "C" void kernel_launch(void* const* d_in, const int* in_sizes, int n_in,
                              void* d_out, int out_size) {
    const float* momery = (const float*)d_in[0];
    const float* hid    = (const float*)d_in[1];
    const float* w      = (const float*)d_in[4];
    const float* wv     = (const float*)d_in[13];
    const float* bv     = (const float*)d_in[14];
    const float* wo     = (const float*)d_in[15];
    const float* bo     = (const float*)d_in[16];
    float* out = (float*)d_out;

    // W = wv @ wo  (split-K partials)
    dim3 gA(DD / 64, DD / 64, KSPLIT);           // (8,8,8)
    k_gemm_w<<<gA, 256>>>(wv, wo);

    // reduce partials
    k_reduce_w<<<(DD * DD / 4) / 256, 256>>>();

    // c = bv @ wo + bo
    k_bias_c<<<DD / 32, 256>>>(bv, wo, bo);

    // temp = 3w * (hid @ W + c)
    dim3 gT(DD / 64, NB / 64);                   // (8,16)
    k_gemm_temp<<<gT, 256>>>(hid, w);

    // out = momery + temp (broadcast over L)
    int n4 = LSLOTS * NB * DD / 4;               // 6,553,600
    k_add<<<6144, 256>>>((const float4*)momery, (float4*)out, n4);
}

// round 2
// speedup vs baseline: 1.3415x; 1.3415x over previous
#include <cuda_runtime.h>

// Problem constants
#define DD      512          // d_model
#define HK      2048         // H*DK
#define NB      1024         // batch
#define LSLOTS  50           // memory slots
#define KSPLIT_W  8
#define KSPLIT_T  4

typedef unsigned long long ull;

// Scratch (static device globals — no allocation)
__device__ float g_Wpart[KSPLIT_W * DD * DD];   // split-K partials for W = wv@wo
__device__ float g_W[DD * DD];                  // fused weight wv@wo
__device__ float g_c[DD];                       // fused bias bv@wo + bo
__device__ float g_Tpart[KSPLIT_T * NB * DD];   // split-K partials for hid@W
__device__ float g_temp[NB * DD];               // final scaled temp

// ---------------------------------------------------------------------------
// f32x2 helpers
// ---------------------------------------------------------------------------
__device__ __forceinline__ ull dup2(float x) {
    ull r; asm("mov.b64 %0, {%1, %1};" : "=l"(r) : "f"(x)); return r;
}
__device__ __forceinline__ void ffma2(ull& d, ull a, ull b) {
    asm("fma.rn.f32x2 %0, %1, %2, %0;" : "+l"(d) : "l"(a), "l"(b));
}
__device__ __forceinline__ void lds_v2u64(ull& a, ull& b, const void* p) {
    unsigned int addr = (unsigned int)__cvta_generic_to_shared(p);
    asm("ld.shared.v2.u64 {%0, %1}, [%2];" : "=l"(a), "=l"(b) : "r"(addr));
}

// ---------------------------------------------------------------------------
// Packed-f32x2 SGEMM: Cpart[z] += A[64-tile, Kchunk] * B[Kchunk, 128-tile]
// Block: 128 threads. Tile M=64, N=128, K-step 16. Micro: 4 rows x 16 cols.
// Thread map: tx = t&7 -> cols {tx*4 + 32p + q}, ty = t>>3 -> rows ty*4..+3
// ---------------------------------------------------------------------------
template<int LDA, int LDB, int KCHUNK, int MTOT, int NTOT>
__global__ __launch_bounds__(128) void gemm2(const float* __restrict__ A,
                                             const float* __restrict__ B,
                                             float* __restrict__ Cpart) {
    __shared__ float As[16][64];    // As[kk][m ^ ((kk>>2)<<3)]  (swizzled)
    __shared__ float Bs[16][128];

    const int t = threadIdx.x;
    const int tx = t & 7;
    const int ty = t >> 3;
    const int nBase = blockIdx.x * 128;
    const int mBase = blockIdx.y * 64;
    const int kb    = blockIdx.z * KCHUNK;

    ull acc[4][8];
#pragma unroll
    for (int i = 0; i < 4; i++)
#pragma unroll
        for (int q = 0; q < 8; q++) acc[i][q] = 0ULL;

    float4 ar[2], br[4];

    auto ldgA = [&](int k0) {
#pragma unroll
        for (int s = 0; s < 2; s++) {
            int f = t + s * 128;
            int m = f >> 2, kq = f & 3;
            ar[s] = *(const float4*)&A[(mBase + m) * LDA + kb + k0 + kq * 4];
        }
    };
    auto ldgB = [&](int k0) {
#pragma unroll
        for (int s = 0; s < 4; s++) {
            int f = t + s * 128;
            int kk = f >> 5, nq = f & 31;
            br[s] = *(const float4*)&B[(kb + k0 + kk) * LDB + nBase + nq * 4];
        }
    };

    constexpr int NIT = KCHUNK / 16;
    ldgA(0); ldgB(0);

    for (int it = 0; it < NIT; ++it) {
        // store staged tiles to smem
#pragma unroll
        for (int s = 0; s < 2; s++) {
            int f = t + s * 128;
            int m = f >> 2, kq = f & 3;
            int col = m ^ (kq << 3);
            As[kq * 4 + 0][col] = ar[s].x;
            As[kq * 4 + 1][col] = ar[s].y;
            As[kq * 4 + 2][col] = ar[s].z;
            As[kq * 4 + 3][col] = ar[s].w;
        }
#pragma unroll
        for (int s = 0; s < 4; s++) {
            int f = t + s * 128;
            int kk = f >> 5, nq = f & 31;
            *(float4*)&Bs[kk][nq * 4] = br[s];
        }
        __syncthreads();

        if (it + 1 < NIT) { ldgA((it + 1) * 16); ldgB((it + 1) * 16); }

#pragma unroll
        for (int kk = 0; kk < 16; kk++) {
            const int sw = ((kk >> 2) & 3) << 3;
            float4 a = *(const float4*)&As[kk][(ty * 4) ^ sw];
            ull a0 = dup2(a.x), a1 = dup2(a.y), a2 = dup2(a.z), a3 = dup2(a.w);
            ull b[8];
#pragma unroll
            for (int p = 0; p < 4; p++)
                lds_v2u64(b[2 * p], b[2 * p + 1], &Bs[kk][tx * 4 + 32 * p]);
#pragma unroll
            for (int q = 0; q < 8; q++) {
                ffma2(acc[0][q], a0, b[q]);
                ffma2(acc[1][q], a1, b[q]);
                ffma2(acc[2][q], a2, b[q]);
                ffma2(acc[3][q], a3, b[q]);
            }
        }
        __syncthreads();
    }

    float* cz = Cpart + (size_t)blockIdx.z * MTOT * NTOT;
#pragma unroll
    for (int i = 0; i < 4; i++) {
        float* crow = cz + (mBase + ty * 4 + i) * NTOT + nBase;
#pragma unroll
        for (int p = 0; p < 4; p++) {
            ulonglong2 v; v.x = acc[i][2 * p]; v.y = acc[i][2 * p + 1];
            *(ulonglong2*)(crow + tx * 4 + 32 * p) = v;
        }
    }
}

// ---------------------------------------------------------------------------
// W = sum of KSPLIT_W partials
// ---------------------------------------------------------------------------
__global__ __launch_bounds__(256) void k_reduce_w() {
    int i = blockIdx.x * blockDim.x + threadIdx.x;   // float4 index
    const float4* p = (const float4*)g_Wpart;
    float4 s = p[i];
#pragma unroll
    for (int k = 1; k < KSPLIT_W; k++) {
        float4 v = p[k * (DD * DD / 4) + i];
        s.x += v.x; s.y += v.y; s.z += v.z; s.w += v.w;
    }
    ((float4*)g_W)[i] = s;
}

// ---------------------------------------------------------------------------
// c[j] = sum_k bv[k]*wo[k,j] + bo[j]
// ---------------------------------------------------------------------------
__global__ __launch_bounds__(256) void k_bias_c(const float* __restrict__ bv,
                                                const float* __restrict__ wo,
                                                const float* __restrict__ bo) {
    __shared__ float red[256];
    const int j0 = blockIdx.x * 32;
    const int t  = threadIdx.x;
    const int tj = t & 31;
    const int kg = t >> 5;
    float acc = 0.0f;
    const int kbeg = kg * 256;
    for (int k = kbeg; k < kbeg + 256; k++)
        acc += bv[k] * wo[k * DD + j0 + tj];
    red[t] = acc;
    __syncthreads();
    if (kg == 0) {
        float s = acc;
#pragma unroll
        for (int g = 1; g < 8; g++) s += red[tj + 32 * g];
        g_c[j0 + tj] = s + bo[j0 + tj];
    }
}

// ---------------------------------------------------------------------------
// temp = 3w * (sum of KSPLIT_T partials + c)
// ---------------------------------------------------------------------------
__global__ __launch_bounds__(256) void k_reduce_temp(const float* __restrict__ wsc) {
    int i = blockIdx.x * blockDim.x + threadIdx.x;   // float4 index over NB*DD/4
    const float4* p = (const float4*)g_Tpart;
    float4 s = p[i];
#pragma unroll
    for (int k = 1; k < KSPLIT_T; k++) {
        float4 v = p[k * (NB * DD / 4) + i];
        s.x += v.x; s.y += v.y; s.z += v.z; s.w += v.w;
    }
    int j4 = i & (DD / 4 - 1);
    float4 c4 = ((const float4*)g_c)[j4];
    float sc = 3.0f * wsc[0];
    s.x = sc * (s.x + c4.x); s.y = sc * (s.y + c4.y);
    s.z = sc * (s.z + c4.z); s.w = sc * (s.w + c4.w);
    ((float4*)g_temp)[i] = s;
}

// ---------------------------------------------------------------------------
// out[l,b,d] = momery[l,b,d] + temp[b,d]
// ---------------------------------------------------------------------------
#define BD4 (NB * DD / 4)   // 131072, power of two

__global__ __launch_bounds__(256) void k_add(const float4* __restrict__ mom,
                                             float4* __restrict__ out, int n4) {
    const float4* tp = (const float4*)g_temp;
    int stride = gridDim.x * blockDim.x;
    for (int i = blockIdx.x * blockDim.x + threadIdx.x; i < n4; i += stride) {
        float4 m = mom[i];
        float4 t = tp[i & (BD4 - 1)];
        m.x += t.x; m.y += t.y; m.z += t.z; m.w += t.w;
        out[i] = m;
    }
}

// ---------------------------------------------------------------------------
// Launch. Inputs (metadata order):
// 0 momery, 1 hid, 2 text_polarity, 3 attribute_polarity, 4 w,
// 5 p_w1, 6 p_b1, 7 p_w2, 8 p_b2, 9 wq, 10 bq, 11 wk, 12 bk,
// 13 wv, 14 bv, 15 wo, 16 bo
// ---------------------------------------------------------------------------
extern "C" void kernel_launch(void* const* d_in, const int* in_sizes, int n_in,
                              void* d_out, int out_size) {
    const float* momery = (const float*)d_in[0];
    const float* hid    = (const float*)d_in[1];
    const float* w      = (const float*)d_in[4];
    const float* wv     = (const float*)d_in[13];
    const float* bv     = (const float*)d_in[14];
    const float* wo     = (const float*)d_in[15];
    const float* bo     = (const float*)d_in[16];
    float* out = (float*)d_out;

    float* wpart; cudaGetSymbolAddress((void**)&wpart, g_Wpart);
    float* wfull; cudaGetSymbolAddress((void**)&wfull, g_W);
    float* tpart; cudaGetSymbolAddress((void**)&tpart, g_Tpart);

    // W partials: wv[512,2048] @ wo[2048,512], split-K 8 (chunks of 256)
    dim3 gW(DD / 128, DD / 64, KSPLIT_W);        // (4, 8, 8) = 256 blocks
    gemm2<HK, DD, HK / KSPLIT_W, DD, DD><<<gW, 128>>>(wv, wo, wpart);

    // reduce W partials
    k_reduce_w<<<(DD * DD / 4) / 256, 256>>>();

    // c = bv @ wo + bo
    k_bias_c<<<DD / 32, 256>>>(bv, wo, bo);

    // temp partials: hid[1024,512] @ W[512,512], split-K 4 (chunks of 128)
    dim3 gT(DD / 128, NB / 64, KSPLIT_T);        // (4, 16, 4) = 256 blocks
    gemm2<DD, DD, DD / KSPLIT_T, NB, DD><<<gT, 128>>>(hid, wfull, tpart);

    // temp = 3w * (sum partials + c)
    k_reduce_temp<<<(NB * DD / 4) / 256, 256>>>(w);

    // out = momery + temp (broadcast over L)
    int n4 = LSLOTS * NB * DD / 4;               // 6,553,600
    k_add<<<6144, 256>>>((const float4*)momery, (float4*)out, n4);
}

// round 4
// speedup vs baseline: 1.6350x; 1.2187x over previous
#include <cuda_runtime.h>
#include <cstdint>

#define DD      512
#define HK      2048
#define NB      1024
#define LSLOTS  50
#define KSW     8            // split-K for W gemm
#define KST     4            // split-K for temp gemm

// Scratch (static device globals — no allocation)
__device__ float g_Wpart[KSW * DD * DD];     // split-K partials of Wt[j,a]
__device__ float g_W[DD * DD];               // Wt[j][a] = (wv@wo)[a][j]
__device__ float g_c[DD];                    // bv@wo + bo
__device__ float g_Tpart[KST * NB * DD];     // split-K partials of hid@Wt^T
__device__ float g_temp[NB * DD];            // 3w*(hid@W + c)

// ---------------------------------------------------------------------------
// helpers
// ---------------------------------------------------------------------------
__device__ __forceinline__ uint32_t f2tf(float x) {
    uint32_t r; asm("cvt.rna.tf32.f32 %0, %1;" : "=r"(r) : "f"(x)); return r;
}
__device__ __forceinline__ void mma8(float* d, const uint32_t* a, const uint32_t* b) {
    asm volatile(
        "mma.sync.aligned.m16n8k8.row.col.f32.tf32.tf32.f32 "
        "{%0,%1,%2,%3}, {%4,%5,%6,%7}, {%8,%9}, {%0,%1,%2,%3};"
        : "+f"(d[0]), "+f"(d[1]), "+f"(d[2]), "+f"(d[3])
        : "r"(a[0]), "r"(a[1]), "r"(a[2]), "r"(a[3]), "r"(b[0]), "r"(b[1]));
}

// ---------------------------------------------------------------------------
// TF32 mma.sync GEMM:  C[z][m,n] = sum_{k in chunk z} A[m,k] * B[n,k]
//   ATR=false: A gmem row-major [m][LDA], K-contig
//   ATR=true : A gmem is [k][LDA] with m-contig rows (i.e. A[m,k] = Ag[k*LDA+m])
//   B gmem row-major [n][LDB], K-contig
// Tile 128x128, Kc=32 per stage, double-buffered smem, 256 threads / 8 warps.
// Warp w: m-off (w&3)*32, n-off (w>>2)*64 -> 2 m-tiles x 8 n-tiles of m16n8k8.
// ---------------------------------------------------------------------------
#define ASZ    4608          // 128*36 words (ATR uses 32*132=4224 of it)
#define BSZ    4608
#define STAGE  (ASZ + BSZ)
#define SMEM_WORDS (2 * STAGE)
#define SMEM_BYTES (SMEM_WORDS * 4)

template<bool ATR, int LDA, int LDB, int MTOT, int NTOT, int KCHUNK>
__global__ __launch_bounds__(256) void gemm_mma(const float* __restrict__ Ag,
                                                const float* __restrict__ Bg,
                                                float* __restrict__ C) {
    extern __shared__ uint32_t smem[];
    const int t = threadIdx.x;
    const int nBase = blockIdx.x * 128;
    const int mBase = blockIdx.y * 128;
    const int kb    = blockIdx.z * KCHUNK;

    // ---- stage-loader thread mapping
    const bool isA = (t < 128);
    const int tt = t & 127;
    const int rr = tt >> 3;        // 0..15 (std: row block)
    const int fc = tt & 7;         // float4 column
    const int jq = tt & 31;        // ATR: float4 of m
    const int kr = tt >> 5;        // ATR: 0..3 k row

    constexpr int NS = KCHUNK / 32;
    float4 rg[8];

#define LDG(s)                                                                  \
    {                                                                           \
        if (isA) {                                                              \
            if (ATR) {                                                          \
                _Pragma("unroll")                                               \
                for (int i = 0; i < 8; ++i)                                     \
                    rg[i] = *(const float4*)&Ag[(size_t)(kb + (s)*32 + kr + 4*i) * LDA \
                                                + mBase + jq * 4];              \
            } else {                                                            \
                _Pragma("unroll")                                               \
                for (int i = 0; i < 8; ++i)                                     \
                    rg[i] = *(const float4*)&Ag[(size_t)(mBase + rr + 16*i) * LDA \
                                                + kb + (s)*32 + fc * 4];        \
            }                                                                   \
        } else {                                                                \
            _Pragma("unroll")                                                   \
            for (int i = 0; i < 8; ++i)                                         \
                rg[i] = *(const float4*)&Bg[(size_t)(nBase + rr + 16*i) * LDB   \
                                            + kb + (s)*32 + fc * 4];            \
        }                                                                       \
    }

    // ---- compute thread mapping
    const int w = t >> 5, lane = t & 31;
    const int moff = (w & 3) * 32;
    const int noff = (w >> 2) * 64;
    const int g = lane >> 2, q = lane & 3;

    float acc[2][8][4];
#pragma unroll
    for (int mt = 0; mt < 2; mt++)
#pragma unroll
        for (int nt = 0; nt < 8; nt++)
#pragma unroll
            for (int r = 0; r < 4; r++) acc[mt][nt][r] = 0.0f;

    LDG(0);

    for (int s = 0; s < NS; ++s) {
        const int buf = s & 1;
        uint32_t* dst = smem + buf * STAGE + (isA ? 0 : ASZ);
        // store staged tile (convert to tf32 once here)
        if (isA && ATR) {
#pragma unroll
            for (int i = 0; i < 8; ++i) {
                uint32_t* p = dst + (kr + 4 * i) * 132 + jq * 4;
                p[0] = f2tf(rg[i].x); p[1] = f2tf(rg[i].y);
                p[2] = f2tf(rg[i].z); p[3] = f2tf(rg[i].w);
            }
        } else {
#pragma unroll
            for (int i = 0; i < 8; ++i) {
                uint32_t* p = dst + (rr + 16 * i) * 36 + fc * 4;
                p[0] = f2tf(rg[i].x); p[1] = f2tf(rg[i].y);
                p[2] = f2tf(rg[i].z); p[3] = f2tf(rg[i].w);
            }
        }
        __syncthreads();
        if (s + 1 < NS) LDG(s + 1);

        const uint32_t* As = smem + buf * STAGE;
        const uint32_t* Bs = As + ASZ;
#pragma unroll
        for (int k0 = 0; k0 < 32; k0 += 8) {
            uint32_t af[2][4];
#pragma unroll
            for (int mt = 0; mt < 2; mt++) {
                const int m0 = moff + mt * 16 + g;
                if (ATR) {
                    af[mt][0] = As[(k0 + q) * 132 + m0];
                    af[mt][1] = As[(k0 + q) * 132 + m0 + 8];
                    af[mt][2] = As[(k0 + q + 4) * 132 + m0];
                    af[mt][3] = As[(k0 + q + 4) * 132 + m0 + 8];
                } else {
                    af[mt][0] = As[m0 * 36 + k0 + q];
                    af[mt][1] = As[(m0 + 8) * 36 + k0 + q];
                    af[mt][2] = As[m0 * 36 + k0 + q + 4];
                    af[mt][3] = As[(m0 + 8) * 36 + k0 + q + 4];
                }
            }
            uint32_t bf[8][2];
#pragma unroll
            for (int nt = 0; nt < 8; nt++) {
                const int n0 = noff + nt * 8 + g;
                bf[nt][0] = Bs[n0 * 36 + k0 + q];
                bf[nt][1] = Bs[n0 * 36 + k0 + q + 4];
            }
#pragma unroll
            for (int mt = 0; mt < 2; mt++)
#pragma unroll
                for (int nt = 0; nt < 8; nt++)
                    mma8(acc[mt][nt], af[mt], bf[nt]);
        }
        __syncthreads();
    }
#undef LDG

    // epilogue: write partials
    float* cz = C + (size_t)blockIdx.z * MTOT * NTOT;
#pragma unroll
    for (int mt = 0; mt < 2; mt++) {
        const int r0 = mBase + moff + mt * 16 + g;
#pragma unroll
        for (int nt = 0; nt < 8; nt++) {
            const int c0 = nBase + noff + nt * 8 + q * 2;
            float2 v0 = make_float2(acc[mt][nt][0], acc[mt][nt][1]);
            float2 v1 = make_float2(acc[mt][nt][2], acc[mt][nt][3]);
            *(float2*)&cz[(size_t)r0 * NTOT + c0] = v0;
            *(float2*)&cz[(size_t)(r0 + 8) * NTOT + c0] = v1;
        }
    }
}

// ---------------------------------------------------------------------------
// W = sum of KSW partials
// ---------------------------------------------------------------------------
__global__ __launch_bounds__(256) void k_reduce_w() {
    int i = blockIdx.x * blockDim.x + threadIdx.x;
    const float4* p = (const float4*)g_Wpart;
    float4 s = p[i];
#pragma unroll
    for (int k = 1; k < KSW; k++) {
        float4 v = p[k * (DD * DD / 4) + i];
        s.x += v.x; s.y += v.y; s.z += v.z; s.w += v.w;
    }
    ((float4*)g_W)[i] = s;
}

// ---------------------------------------------------------------------------
// c[j] = sum_k bv[k]*wo[k,j] + bo[j]
// ---------------------------------------------------------------------------
__global__ __launch_bounds__(256) void k_bias_c(const float* __restrict__ bv,
                                                const float* __restrict__ wo,
                                                const float* __restrict__ bo) {
    __shared__ float red[256];
    const int j0 = blockIdx.x * 32;
    const int t  = threadIdx.x;
    const int tj = t & 31;
    const int kg = t >> 5;
    float acc = 0.0f;
    const int kbeg = kg * 256;
    for (int k = kbeg; k < kbeg + 256; k++)
        acc += bv[k] * wo[k * DD + j0 + tj];
    red[t] = acc;
    __syncthreads();
    if (kg == 0) {
        float s = acc;
#pragma unroll
        for (int g = 1; g < 8; g++) s += red[tj + 32 * g];
        g_c[j0 + tj] = s + bo[j0 + tj];
    }
}

// ---------------------------------------------------------------------------
// temp = 3w * (sum of KST partials + c)
// ---------------------------------------------------------------------------
__global__ __launch_bounds__(256) void k_reduce_temp(const float* __restrict__ wsc) {
    int i = blockIdx.x * blockDim.x + threadIdx.x;   // float4 over NB*DD/4
    const float4* p = (const float4*)g_Tpart;
    float4 s = p[i];
#pragma unroll
    for (int k = 1; k < KST; k++) {
        float4 v = p[k * (NB * DD / 4) + i];
        s.x += v.x; s.y += v.y; s.z += v.z; s.w += v.w;
    }
    int j4 = i & (DD / 4 - 1);
    float4 c4 = ((const float4*)g_c)[j4];
    float sc = 3.0f * wsc[0];
    s.x = sc * (s.x + c4.x); s.y = sc * (s.y + c4.y);
    s.z = sc * (s.z + c4.z); s.w = sc * (s.w + c4.w);
    ((float4*)g_temp)[i] = s;
}

// ---------------------------------------------------------------------------
// out[l,b,d] = momery[l,b,d] + temp[b,d]
// ---------------------------------------------------------------------------
#define BD4 (NB * DD / 4)   // 131072, power of two

__global__ __launch_bounds__(256) void k_add(const float4* __restrict__ mom,
                                             float4* __restrict__ out, int n4) {
    const float4* tp = (const float4*)g_temp;
    int stride = gridDim.x * blockDim.x;
    for (int i = blockIdx.x * blockDim.x + threadIdx.x; i < n4; i += stride) {
        float4 m = mom[i];
        float4 tv = tp[i & (BD4 - 1)];
        m.x += tv.x; m.y += tv.y; m.z += tv.z; m.w += tv.w;
        out[i] = m;
    }
}

// ---------------------------------------------------------------------------
// Launch. Inputs (metadata order):
// 0 momery, 1 hid, 2 text_polarity, 3 attribute_polarity, 4 w,
// 5 p_w1, 6 p_b1, 7 p_w2, 8 p_b2, 9 wq, 10 bq, 11 wk, 12 bk,
// 13 wv, 14 bv, 15 wo, 16 bo
// ---------------------------------------------------------------------------
extern "C" void kernel_launch(void* const* d_in, const int* in_sizes, int n_in,
                              void* d_out, int out_size) {
    const float* momery = (const float*)d_in[0];
    const float* hid    = (const float*)d_in[1];
    const float* w      = (const float*)d_in[4];
    const float* wv     = (const float*)d_in[13];
    const float* bv     = (const float*)d_in[14];
    const float* wo     = (const float*)d_in[15];
    const float* bo     = (const float*)d_in[16];
    float* out = (float*)d_out;

    float* wpart; cudaGetSymbolAddress((void**)&wpart, g_Wpart);
    float* wfull; cudaGetSymbolAddress((void**)&wfull, g_W);
    float* tpart; cudaGetSymbolAddress((void**)&tpart, g_Tpart);

    // Wt[j,a] = sum_k wo[k,j] * wv[a,k]   (A = wo transposed-staged, B = wv)
    auto gw = gemm_mma<true, DD, HK, DD, DD, HK / KSW>;
    // Tpart[b,j] = sum_a hid[b,a] * Wt[j,a]
    auto gt = gemm_mma<false, DD, DD, NB, DD, DD / KST>;
    cudaFuncSetAttribute(gw, cudaFuncAttributeMaxDynamicSharedMemorySize, SMEM_BYTES);
    cudaFuncSetAttribute(gt, cudaFuncAttributeMaxDynamicSharedMemorySize, SMEM_BYTES);

    // 1. c = bv @ wo + bo
    k_bias_c<<<DD / 32, 256>>>(bv, wo, bo);

    // 2. Wt partials (split-K 8): grid (n=4, m=4, z=8) = 128 blocks
    gw<<<dim3(DD / 128, DD / 128, KSW), 256, SMEM_BYTES>>>(wo, wv, wpart);

    // 3. reduce Wt partials
    k_reduce_w<<<(DD * DD / 4) / 256, 256>>>();

    // 4. temp partials (split-K 4): grid (n=4, m=8, z=4) = 128 blocks
    gt<<<dim3(DD / 128, NB / 128, KST), 256, SMEM_BYTES>>>(hid, wfull, tpart);

    // 5. temp = 3w * (sum partials + c)
    k_reduce_temp<<<(NB * DD / 4) / 256, 256>>>(w);

    // 6. out = momery + temp (broadcast over L)
    int n4 = LSLOTS * NB * DD / 4;
    k_add<<<6144, 256>>>((const float4*)momery, (float4*)out, n4);
}

// round 5
// speedup vs baseline: 1.8720x; 1.1450x over previous
#include <cuda_runtime.h>
#include <cstdint>

#define DD      512
#define HK      2048
#define NB      1024
#define LSLOTS  50
#define KSW     8            // split-K for W gemm
#define KST     4            // split-K for temp gemm
#define NBLK    128          // persistent grid size

// Scratch (static device globals — no allocation)
__device__ float g_Wpart[KSW * DD * DD];     // split-K partials of Wt[j,a]
__device__ float g_W[DD * DD];               // Wt[j][a] = (wv@wo)[a][j]
__device__ float g_c[DD];                    // bv@wo + bo
__device__ float g_Tpart[KST * NB * DD];     // split-K partials of hid@Wt^T
__device__ float g_temp[NB * DD];            // 3w*(hid@W + c)

// grid barrier state (generation persists across replays; monotone)
__device__ int g_bar_count = 0;
__device__ volatile int g_bar_gen = 0;

__device__ __forceinline__ void grid_bar() {
    __syncthreads();
    if (threadIdx.x == 0) {
        __threadfence();
        int gen = g_bar_gen;
        if (atomicAdd(&g_bar_count, 1) == NBLK - 1) {
            g_bar_count = 0;
            __threadfence();
            g_bar_gen = gen + 1;
        } else {
            while (g_bar_gen == gen) { }
        }
        __threadfence();
    }
    __syncthreads();
}

// ---------------------------------------------------------------------------
// helpers
// ---------------------------------------------------------------------------
__device__ __forceinline__ uint32_t f2tf(float x) {
    uint32_t r; asm("cvt.rna.tf32.f32 %0, %1;" : "=r"(r) : "f"(x)); return r;
}
__device__ __forceinline__ void mma8(float* d, const uint32_t* a, const uint32_t* b) {
    asm volatile(
        "mma.sync.aligned.m16n8k8.row.col.f32.tf32.tf32.f32 "
        "{%0,%1,%2,%3}, {%4,%5,%6,%7}, {%8,%9}, {%0,%1,%2,%3};"
        : "+f"(d[0]), "+f"(d[1]), "+f"(d[2]), "+f"(d[3])
        : "r"(a[0]), "r"(a[1]), "r"(a[2]), "r"(a[3]), "r"(b[0]), "r"(b[1]));
}

// ---------------------------------------------------------------------------
// TF32 mma.sync GEMM device fn: C[z][m,n] = sum_{k in chunk z} A[m,k]*B[n,k]
//   ATR=false: A row-major [m][LDA] K-contig; ATR=true: A is [k][LDA] m-contig.
// Tile 128x128, Kc=32 per stage, double-buffered smem, 256 threads / 8 warps.
// ---------------------------------------------------------------------------
#define ASZ    4608          // 128*36 words (ATR uses 32*132=4224 of it)
#define BSZ    4608
#define STAGE  (ASZ + BSZ)
#define SMEM_WORDS (2 * STAGE)
#define SMEM_BYTES (SMEM_WORDS * 4)

template<bool ATR, int LDA, int LDB, int MTOT, int NTOT, int KCHUNK>
__device__ __forceinline__ void gemm_dev(const float* __restrict__ Ag,
                                         const float* __restrict__ Bg,
                                         float* __restrict__ C,
                                         uint32_t* smem,
                                         int bx, int by, int bz) {
    const int t = threadIdx.x;
    const int nBase = bx * 128;
    const int mBase = by * 128;
    const int kb    = bz * KCHUNK;

    const bool isA = (t < 128);
    const int tt = t & 127;
    const int rr = tt >> 3;
    const int fc = tt & 7;
    const int jq = tt & 31;
    const int kr = tt >> 5;

    constexpr int NS = KCHUNK / 32;
    float4 rg[8];

#define LDG(s)                                                                  \
    {                                                                           \
        if (isA) {                                                              \
            if (ATR) {                                                          \
                _Pragma("unroll")                                               \
                for (int i = 0; i < 8; ++i)                                     \
                    rg[i] = *(const float4*)&Ag[(size_t)(kb + (s)*32 + kr + 4*i) * LDA \
                                                + mBase + jq * 4];              \
            } else {                                                            \
                _Pragma("unroll")                                               \
                for (int i = 0; i < 8; ++i)                                     \
                    rg[i] = *(const float4*)&Ag[(size_t)(mBase + rr + 16*i) * LDA \
                                                + kb + (s)*32 + fc * 4];        \
            }                                                                   \
        } else {                                                                \
            _Pragma("unroll")                                                   \
            for (int i = 0; i < 8; ++i)                                         \
                rg[i] = *(const float4*)&Bg[(size_t)(nBase + rr + 16*i) * LDB   \
                                            + kb + (s)*32 + fc * 4];            \
        }                                                                       \
    }

    const int w = t >> 5, lane = t & 31;
    const int moff = (w & 3) * 32;
    const int noff = (w >> 2) * 64;
    const int g = lane >> 2, q = lane & 3;

    float acc[2][8][4];
#pragma unroll
    for (int mt = 0; mt < 2; mt++)
#pragma unroll
        for (int nt = 0; nt < 8; nt++)
#pragma unroll
            for (int r = 0; r < 4; r++) acc[mt][nt][r] = 0.0f;

    LDG(0);

    for (int s = 0; s < NS; ++s) {
        const int buf = s & 1;
        uint32_t* dst = smem + buf * STAGE + (isA ? 0 : ASZ);
        if (isA && ATR) {
#pragma unroll
            for (int i = 0; i < 8; ++i) {
                uint32_t* p = dst + (kr + 4 * i) * 132 + jq * 4;
                p[0] = f2tf(rg[i].x); p[1] = f2tf(rg[i].y);
                p[2] = f2tf(rg[i].z); p[3] = f2tf(rg[i].w);
            }
        } else {
#pragma unroll
            for (int i = 0; i < 8; ++i) {
                uint32_t* p = dst + (rr + 16 * i) * 36 + fc * 4;
                p[0] = f2tf(rg[i].x); p[1] = f2tf(rg[i].y);
                p[2] = f2tf(rg[i].z); p[3] = f2tf(rg[i].w);
            }
        }
        __syncthreads();
        if (s + 1 < NS) LDG(s + 1);

        const uint32_t* As = smem + buf * STAGE;
        const uint32_t* Bs = As + ASZ;
#pragma unroll
        for (int k0 = 0; k0 < 32; k0 += 8) {
            uint32_t af[2][4];
#pragma unroll
            for (int mt = 0; mt < 2; mt++) {
                const int m0 = moff + mt * 16 + g;
                if (ATR) {
                    af[mt][0] = As[(k0 + q) * 132 + m0];
                    af[mt][1] = As[(k0 + q) * 132 + m0 + 8];
                    af[mt][2] = As[(k0 + q + 4) * 132 + m0];
                    af[mt][3] = As[(k0 + q + 4) * 132 + m0 + 8];
                } else {
                    af[mt][0] = As[m0 * 36 + k0 + q];
                    af[mt][1] = As[(m0 + 8) * 36 + k0 + q];
                    af[mt][2] = As[m0 * 36 + k0 + q + 4];
                    af[mt][3] = As[(m0 + 8) * 36 + k0 + q + 4];
                }
            }
            uint32_t bf[8][2];
#pragma unroll
            for (int nt = 0; nt < 8; nt++) {
                const int n0 = noff + nt * 8 + g;
                bf[nt][0] = Bs[n0 * 36 + k0 + q];
                bf[nt][1] = Bs[n0 * 36 + k0 + q + 4];
            }
#pragma unroll
            for (int mt = 0; mt < 2; mt++)
#pragma unroll
                for (int nt = 0; nt < 8; nt++)
                    mma8(acc[mt][nt], af[mt], bf[nt]);
        }
        __syncthreads();
    }
#undef LDG

    float* cz = C + (size_t)bz * MTOT * NTOT;
#pragma unroll
    for (int mt = 0; mt < 2; mt++) {
        const int r0 = mBase + moff + mt * 16 + g;
#pragma unroll
        for (int nt = 0; nt < 8; nt++) {
            const int c0 = nBase + noff + nt * 8 + q * 2;
            float2 v0 = make_float2(acc[mt][nt][0], acc[mt][nt][1]);
            float2 v1 = make_float2(acc[mt][nt][2], acc[mt][nt][3]);
            *(float2*)&cz[(size_t)r0 * NTOT + c0] = v0;
            *(float2*)&cz[(size_t)(r0 + 8) * NTOT + c0] = v1;
        }
    }
}

// ---------------------------------------------------------------------------
// Fused persistent kernel: P0 gemm_w | P1 reduce_w + bias_c | P2 gemm_temp |
// P3 reduce_temp.  Grid = NBLK blocks, 256 threads.
// ---------------------------------------------------------------------------
__global__ __launch_bounds__(256) void k_fused(const float* __restrict__ wo,
                                               const float* __restrict__ wv,
                                               const float* __restrict__ hid,
                                               const float* __restrict__ bv,
                                               const float* __restrict__ bo,
                                               const float* __restrict__ wsc) {
    extern __shared__ uint32_t smem[];
    __shared__ float sred[8];
    const int b = blockIdx.x;
    const int t = threadIdx.x;

    // ---- P0: Wt partials  Wt[j,a] = sum_k wo[k,j] * wv[a,k]
    gemm_dev<true, DD, HK, DD, DD, HK / KSW>(wo, wv, g_Wpart, smem,
                                             b & 3, (b >> 2) & 3, b >> 4);
    grid_bar();

    // ---- P1a: reduce W partials (65536 float4 over 128 blocks => 2/thread)
    {
        const float4* p = (const float4*)g_Wpart;
#pragma unroll
        for (int u = 0; u < 2; ++u) {
            int i = b * 512 + u * 256 + t;
            float4 s = p[i];
#pragma unroll
            for (int k = 1; k < KSW; k++) {
                float4 v = p[k * (DD * DD / 4) + i];
                s.x += v.x; s.y += v.y; s.z += v.z; s.w += v.w;
            }
            ((float4*)g_W)[i] = s;
        }
    }
    // ---- P1b: bias c[j] = sum_k bv[k]*wo[k,j] + bo[j]  (4 j's per block)
    {
        const int j = b * 4 + (t >> 6);
        const int l64 = t & 63;
        float acc = 0.0f;
        const int k0 = l64 * 32;
        for (int k = k0; k < k0 + 32; k++)
            acc += bv[k] * wo[(size_t)k * DD + j];
#pragma unroll
        for (int off = 16; off > 0; off >>= 1)
            acc += __shfl_down_sync(0xFFFFFFFFu, acc, off);
        if ((t & 31) == 0) sred[t >> 5] = acc;
        __syncthreads();
        if (t < 4) g_c[b * 4 + t] = sred[2 * t] + sred[2 * t + 1] + bo[b * 4 + t];
    }
    grid_bar();

    // ---- P2: temp partials  Tpart[z][b,j] = sum_a hid[b,a]*Wt[j,a]
    gemm_dev<false, DD, DD, NB, DD, DD / KST>(hid, g_W, g_Tpart, smem,
                                              b & 3, (b >> 2) & 7, b >> 5);
    grid_bar();

    // ---- P3: temp = 3w * (sum partials + c)   (131072 float4 => 4/thread)
    {
        const float sc = 3.0f * wsc[0];
        const float4* p = (const float4*)g_Tpart;
#pragma unroll
        for (int u = 0; u < 4; ++u) {
            int i = b * 1024 + u * 256 + t;
            float4 s = p[i];
#pragma unroll
            for (int k = 1; k < KST; k++) {
                float4 v = p[k * (NB * DD / 4) + i];
                s.x += v.x; s.y += v.y; s.z += v.z; s.w += v.w;
            }
            float4 c4 = ((const float4*)g_c)[i & (DD / 4 - 1)];
            s.x = sc * (s.x + c4.x); s.y = sc * (s.y + c4.y);
            s.z = sc * (s.z + c4.z); s.w = sc * (s.w + c4.w);
            ((float4*)g_temp)[i] = s;
        }
    }
}

// ---------------------------------------------------------------------------
// out[l,b,d] = momery[l,b,d] + temp[b,d]
// ---------------------------------------------------------------------------
#define BD4 (NB * DD / 4)   // 131072, power of two

__global__ __launch_bounds__(256) void k_add(const float4* __restrict__ mom,
                                             float4* __restrict__ out, int n4) {
    const float4* tp = (const float4*)g_temp;
    int stride = gridDim.x * blockDim.x;
    for (int i = blockIdx.x * blockDim.x + threadIdx.x; i < n4; i += stride) {
        float4 m = mom[i];
        float4 tv = tp[i & (BD4 - 1)];
        m.x += tv.x; m.y += tv.y; m.z += tv.z; m.w += tv.w;
        out[i] = m;
    }
}

// ---------------------------------------------------------------------------
// Launch. Inputs (metadata order):
// 0 momery, 1 hid, 2 text_polarity, 3 attribute_polarity, 4 w,
// 5 p_w1, 6 p_b1, 7 p_w2, 8 p_b2, 9 wq, 10 bq, 11 wk, 12 bk,
// 13 wv, 14 bv, 15 wo, 16 bo
// ---------------------------------------------------------------------------
extern "C" void kernel_launch(void* const* d_in, const int* in_sizes, int n_in,
                              void* d_out, int out_size) {
    const float* momery = (const float*)d_in[0];
    const float* hid    = (const float*)d_in[1];
    const float* w      = (const float*)d_in[4];
    const float* wv     = (const float*)d_in[13];
    const float* bv     = (const float*)d_in[14];
    const float* wo     = (const float*)d_in[15];
    const float* bo     = (const float*)d_in[16];
    float* out = (float*)d_out;

    cudaFuncSetAttribute(k_fused, cudaFuncAttributeMaxDynamicSharedMemorySize,
                         SMEM_BYTES);

    k_fused<<<NBLK, 256, SMEM_BYTES>>>(wo, wv, hid, bv, bo, w);

    int n4 = LSLOTS * NB * DD / 4;
    k_add<<<6144, 256>>>((const float4*)momery, (float4*)out, n4);
}